// round 5
// baseline (speedup 1.0000x reference)
#include <cuda_runtime.h>

// Problem constants (fixed by the dataset)
#define NBATCH 16384
#define NS 256
#define NH 128
#define NA 18
#define NT 8
#define NR 2   // batch rows per block

// Folded non-spiking-LIF + mean-over-T weights: w_t = (1 - 2^{-(T-t)})/T
#define SW_TOTAL 0.87548828125f

typedef unsigned long long u64;

// ---- packed fp32x2 helpers (sm_103a) ----
__device__ __forceinline__ u64 pack2(float a, float b) {
    u64 r;
    asm("mov.b64 %0, {%1, %2};" : "=l"(r) : "f"(a), "f"(b));
    return r;
}
__device__ __forceinline__ void unpack2(u64 v, float& a, float& b) {
    asm("mov.b64 {%0, %1}, %2;" : "=f"(a), "=f"(b) : "l"(v));
}
__device__ __forceinline__ void fma2(u64& acc, u64 ab, u64 cd) {
    asm("fma.rn.f32x2 %0, %1, %2, %3;" : "=l"(acc) : "l"(ab), "l"(cd), "l"(acc));
}

__device__ __forceinline__ void block_ln_stats(
    float u0, float u1, float (&red)[2][16], int t, int lane, int wid,
    float& mu0, float& rs0, float& mu1, float& rs1)
{
    float s0 = u0, q0 = u0 * u0, s1 = u1, q1 = u1 * u1;
    #pragma unroll
    for (int o = 16; o > 0; o >>= 1) {
        s0 += __shfl_xor_sync(0xffffffffu, s0, o);
        q0 += __shfl_xor_sync(0xffffffffu, q0, o);
        s1 += __shfl_xor_sync(0xffffffffu, s1, o);
        q1 += __shfl_xor_sync(0xffffffffu, q1, o);
    }
    float* rb = red[t & 1];
    if (lane == 0) { rb[wid] = s0; rb[4 + wid] = q0; rb[8 + wid] = s1; rb[12 + wid] = q1; }
    __syncthreads();
    float S0 = rb[0] + rb[1] + rb[2] + rb[3];
    float Q0 = rb[4] + rb[5] + rb[6] + rb[7];
    float S1 = rb[8] + rb[9] + rb[10] + rb[11];
    float Q1 = rb[12] + rb[13] + rb[14] + rb[15];
    mu0 = S0 * (1.f / NH);
    mu1 = S1 * (1.f / NH);
    float v0 = Q0 * (1.f / NH) - mu0 * mu0;
    float v1 = Q1 * (1.f / NH) - mu1 * mu1;
    rs0 = rsqrtf(v0 + 1e-5f);
    rs1 = rsqrtf(v1 + 1e-5f);
}

// One MS_ResBlock for NR=2 rows, all NT timesteps.
// hin: input spikes [NT][NH][NR]; hout: output spikes (written unless FINAL).
// If FINAL: accumulate hacc += w_t * spike instead of storing spikes.
template <bool FINAL>
__device__ __forceinline__ void res_block(
    const float* __restrict__ W, float bb, float gg, float bt,
    const float (&hin)[NT][NH][NR], float (&hout)[NT][NH][NR],
    float (&red)[2][16], int h, int lane, int wid,
    float& hacc0, float& hacc1)
{
    constexpr float WT[NT] = {
        0.12451171875f, 0.1240234375f, 0.123046875f, 0.12109375f,
        0.1171875f, 0.109375f, 0.09375f, 0.0625f
    };

    // GEMM: u[t] = (bb,bb) + sum_j hin[t][j][:] * W[j][h]  (packed over r)
    u64 u2[NT];
    #pragma unroll
    for (int t = 0; t < NT; t++) u2[t] = pack2(bb, bb);

    #pragma unroll 4
    for (int j = 0; j < NH; j += 2) {
        float w0 = W[j * NH + h];
        float w1 = W[(j + 1) * NH + h];
        u64 w02 = pack2(w0, w0);
        u64 w12 = pack2(w1, w1);
        #pragma unroll
        for (int t = 0; t < NT; t++) {
            ulonglong2 p = *(const ulonglong2*)&hin[t][j][0];
            fma2(u2[t], p.x, w02);
            fma2(u2[t], p.y, w12);
        }
    }

    // LN + residual + LIF (sequential over t)
    float v0 = 0.f, v1 = 0.f;
    #pragma unroll
    for (int t = 0; t < NT; t++) {
        float ut0, ut1;
        unpack2(u2[t], ut0, ut1);
        float mu0, rs0, mu1, rs1;
        block_ln_stats(ut0, ut1, red, t, lane, wid, mu0, rs0, mu1, rs1);
        float r0, r1;
        unpack2(*(const u64*)&hin[t][h][0], r0, r1);
        float li0 = (ut0 - mu0) * rs0 * gg + bt + r0;
        float li1 = (ut1 - mu1) * rs1 * gg + bt + r1;
        v0 += (li0 - v0) * 0.5f;
        v1 += (li1 - v1) * 0.5f;
        float sp0 = (v0 >= 1.f) ? 1.f : 0.f;
        float sp1 = (v1 >= 1.f) ? 1.f : 0.f;
        if (FINAL) {
            hacc0 = fmaf(WT[t], sp0, hacc0);
            hacc1 = fmaf(WT[t], sp1, hacc1);
        } else {
            hout[t][h][0] = sp0;
            hout[t][h][1] = sp1;
        }
        v0 *= (1.f - sp0);
        v1 *= (1.f - sp1);
    }
    __syncthreads();
}

__global__ __launch_bounds__(128)
void snn_fused_kernel(
    const float* __restrict__ x,     // [B,S]
    const float* __restrict__ enc,   // [T,B,S]
    const float* __restrict__ W_in,  // [S,H]
    const float* __restrict__ b_in,  // [H]
    const float* __restrict__ W_r1, const float* __restrict__ b_r1,
    const float* __restrict__ g_r1, const float* __restrict__ be_r1,
    const float* __restrict__ W_r2, const float* __restrict__ b_r2,
    const float* __restrict__ g_r2, const float* __restrict__ be_r2,
    const float* __restrict__ W_out, const float* __restrict__ b_out,
    float* __restrict__ out)         // [B,A]
{
    __shared__ __align__(16) float spk[NT][NS][NR];   // 16 KB encoder spikes (r-paired)
    __shared__ __align__(16) float hb1[NT][NH][NR];   // 8 KB spikes after LIF1 / scratch
    __shared__ __align__(16) float hb2[NT][NH][NR];   // 8 KB spikes after block1
    __shared__ float xs[NR][NS];        // 2 KB staged x rows
    __shared__ float red[2][16];        // LN reduction scratch (double-buffered)
    __shared__ float ha[NR][NH];        // weighted spike accumulator for output GEMM

    const int h = threadIdx.x;
    const int b0 = blockIdx.x * NR;
    const int lane = h & 31, wid = h >> 5;

    // ---- Stage x rows (each thread owns s = h, h+128; read back by same thread) ----
    #pragma unroll
    for (int r = 0; r < NR; r++)
        #pragma unroll
        for (int s = h; s < NS; s += 128)
            xs[r][s] = x[(b0 + r) * NS + s];

    // ---- Poisson encoder: spike = (enc_rand <= x) ----
    #pragma unroll
    for (int t = 0; t < NT; t++)
        #pragma unroll
        for (int r = 0; r < NR; r++)
            #pragma unroll
            for (int s = h; s < NS; s += 128) {
                float e = enc[(t * NBATCH + (b0 + r)) * NS + s];
                spk[t][s][r] = (e <= xs[r][s]) ? 1.f : 0.f;
            }
    __syncthreads();

    // ---- Layer 1 GEMM: u[t] = b_in[h] + sum_s spk[t][s][:] * W_in[s][h] ----
    u64 u2[NT];
    {
        const float bin = b_in[h];
        #pragma unroll
        for (int t = 0; t < NT; t++) u2[t] = pack2(bin, bin);

        #pragma unroll 4
        for (int s = 0; s < NS; s += 2) {
            float w0 = W_in[s * NH + h];
            float w1 = W_in[(s + 1) * NH + h];
            u64 w02 = pack2(w0, w0);
            u64 w12 = pack2(w1, w1);
            #pragma unroll
            for (int t = 0; t < NT; t++) {
                ulonglong2 p = *(const ulonglong2*)&spk[t][s][0];
                fma2(u2[t], p.x, w02);
                fma2(u2[t], p.y, w12);
            }
        }
    }

    // ---- LIF1: v += (u - v)/2; spike = (v >= 1); hard reset ----
    {
        float v0 = 0.f, v1 = 0.f;
        #pragma unroll
        for (int t = 0; t < NT; t++) {
            float ut0, ut1;
            unpack2(u2[t], ut0, ut1);
            v0 += (ut0 - v0) * 0.5f;
            v1 += (ut1 - v1) * 0.5f;
            float sp0 = (v0 >= 1.f) ? 1.f : 0.f;
            float sp1 = (v1 >= 1.f) ? 1.f : 0.f;
            hb1[t][h][0] = sp0;
            hb1[t][h][1] = sp1;
            v0 *= (1.f - sp0);
            v1 *= (1.f - sp1);
        }
    }
    __syncthreads();

    float hacc0 = 0.f, hacc1 = 0.f;

    // ---- ResBlock 1: hb1 -> hb2 ----
    res_block<false>(W_r1, b_r1[h], g_r1[h], be_r1[h],
                     hb1, hb2, red, h, lane, wid, hacc0, hacc1);

    // ---- ResBlock 2 (final): hb2 -> weighted accumulator ----
    res_block<true>(W_r2, b_r2[h], g_r2[h], be_r2[h],
                    hb2, hb1, red, h, lane, wid, hacc0, hacc1);

    // ---- Output head: q[r][a] = sum_h hacc * W_out[h][a] + b_out[a]*SW ----
    ha[0][h] = hacc0;
    ha[1][h] = hacc1;
    __syncthreads();

    if (h < NR * NA) {
        int r = h / NA, a = h % NA;
        float sum = b_out[a] * SW_TOTAL;
        #pragma unroll
        for (int j = 0; j < NH; j++)
            sum = fmaf(ha[r][j], W_out[j * NA + a], sum);
        out[(b0 + r) * NA + a] = sum;
    }
}

extern "C" void kernel_launch(void* const* d_in, const int* in_sizes, int n_in,
                              void* d_out, int out_size)
{
    const float* x      = (const float*)d_in[0];
    const float* enc    = (const float*)d_in[1];
    const float* W_in   = (const float*)d_in[2];
    const float* b_in   = (const float*)d_in[3];
    const float* W_r1   = (const float*)d_in[4];
    const float* b_r1   = (const float*)d_in[5];
    const float* g_r1   = (const float*)d_in[6];
    const float* be_r1  = (const float*)d_in[7];
    const float* W_r2   = (const float*)d_in[8];
    const float* b_r2   = (const float*)d_in[9];
    const float* g_r2   = (const float*)d_in[10];
    const float* be_r2  = (const float*)d_in[11];
    const float* W_out  = (const float*)d_in[12];
    const float* b_out  = (const float*)d_in[13];
    float* out = (float*)d_out;

    dim3 grid(NBATCH / NR);
    dim3 block(128);
    snn_fused_kernel<<<grid, block>>>(
        x, enc, W_in, b_in, W_r1, b_r1, g_r1, be_r1,
        W_r2, b_r2, g_r2, be_r2, W_out, b_out, out);
}

// round 10
// speedup vs baseline: 1.0602x; 1.0602x over previous
#include <cuda_runtime.h>

// Problem constants (fixed by the dataset)
#define NBATCH 16384
#define NS 256
#define NH 128
#define NA 18
#define NT 8
#define NR 2        // batch rows per block
#define NTHREADS 32 // single warp; each thread owns 4 h columns: tid + 32c
#define NC 4

// Folded non-spiking-LIF + mean-over-T weights: w_t = (1 - 2^{-(T-t)})/T
#define SW_TOTAL 0.87548828125f

typedef unsigned long long u64;

// ---- packed fp32x2 helpers (sm_103a) ----
__device__ __forceinline__ u64 pack2(float a, float b) {
    u64 r;
    asm("mov.b64 %0, {%1, %2};" : "=l"(r) : "f"(a), "f"(b));
    return r;
}
__device__ __forceinline__ void unpack2(u64 v, float& a, float& b) {
    asm("mov.b64 {%0, %1}, %2;" : "=f"(a), "=f"(b) : "l"(v));
}
__device__ __forceinline__ void fma2(u64& acc, u64 ab, u64 cd) {
    asm("fma.rn.f32x2 %0, %1, %2, %3;" : "=l"(acc) : "l"(ab), "l"(cd), "l"(acc));
}

// Warp-wide LN stats over NH=128 (4 cols/thread already pre-summed), both rows.
__device__ __forceinline__ void warp_ln_stats(
    float s0, float q0, float s1, float q1,
    float& mu0, float& rs0, float& mu1, float& rs1)
{
    #pragma unroll
    for (int o = 16; o > 0; o >>= 1) {
        s0 += __shfl_xor_sync(0xffffffffu, s0, o);
        q0 += __shfl_xor_sync(0xffffffffu, q0, o);
        s1 += __shfl_xor_sync(0xffffffffu, s1, o);
        q1 += __shfl_xor_sync(0xffffffffu, q1, o);
    }
    mu0 = s0 * (1.f / NH);
    mu1 = s1 * (1.f / NH);
    float v0 = q0 * (1.f / NH) - mu0 * mu0;
    float v1 = q1 * (1.f / NH) - mu1 * mu1;
    rs0 = rsqrtf(v0 + 1e-5f);
    rs1 = rsqrtf(v1 + 1e-5f);
}

// One MS_ResBlock for NR=2 rows, all NT timesteps, NC=4 columns per thread.
template <bool FINAL>
__device__ __forceinline__ void res_block(
    const float* __restrict__ W,
    const float (&bb)[NC], const float (&gg)[NC], const float (&bt)[NC],
    const float (&hin)[NT][NH][NR], float (&hout)[NT][NH][NR],
    int tid, float (&hacc)[NC][NR])
{
    constexpr float WT[NT] = {
        0.12451171875f, 0.1240234375f, 0.123046875f, 0.12109375f,
        0.1171875f, 0.109375f, 0.09375f, 0.0625f
    };

    // GEMM: u2[t][c] = (bb[c],bb[c]) + sum_j hin[t][j][:] * W[j][tid+32c]
    u64 u2[NT][NC];
    #pragma unroll
    for (int t = 0; t < NT; t++)
        #pragma unroll
        for (int c = 0; c < NC; c++)
            u2[t][c] = pack2(bb[c], bb[c]);

    #pragma unroll 2
    for (int j = 0; j < NH; j += 2) {
        u64 wA[NC], wB[NC];
        #pragma unroll
        for (int c = 0; c < NC; c++) {
            float a = W[j * NH + tid + 32 * c];
            float b = W[(j + 1) * NH + tid + 32 * c];
            wA[c] = pack2(a, a);
            wB[c] = pack2(b, b);
        }
        #pragma unroll
        for (int t = 0; t < NT; t++) {
            ulonglong2 p = *(const ulonglong2*)&hin[t][j][0];
            #pragma unroll
            for (int c = 0; c < NC; c++) {
                fma2(u2[t][c], p.x, wA[c]);
                fma2(u2[t][c], p.y, wB[c]);
            }
        }
    }

    // LN + residual + LIF (sequential over t) — all warp-local, no barriers
    float v[NC][NR];
    #pragma unroll
    for (int c = 0; c < NC; c++) { v[c][0] = 0.f; v[c][1] = 0.f; }

    #pragma unroll
    for (int t = 0; t < NT; t++) {
        float u[NC][NR];
        float s0 = 0.f, q0 = 0.f, s1 = 0.f, q1 = 0.f;
        #pragma unroll
        for (int c = 0; c < NC; c++) {
            unpack2(u2[t][c], u[c][0], u[c][1]);
            s0 += u[c][0]; q0 += u[c][0] * u[c][0];
            s1 += u[c][1]; q1 += u[c][1] * u[c][1];
        }
        float mu0, rs0, mu1, rs1;
        warp_ln_stats(s0, q0, s1, q1, mu0, rs0, mu1, rs1);

        #pragma unroll
        for (int c = 0; c < NC; c++) {
            float r0, r1;
            unpack2(*(const u64*)&hin[t][tid + 32 * c][0], r0, r1);
            float li0 = (u[c][0] - mu0) * rs0 * gg[c] + bt[c] + r0;
            float li1 = (u[c][1] - mu1) * rs1 * gg[c] + bt[c] + r1;
            v[c][0] += (li0 - v[c][0]) * 0.5f;
            v[c][1] += (li1 - v[c][1]) * 0.5f;
            float sp0 = (v[c][0] >= 1.f) ? 1.f : 0.f;
            float sp1 = (v[c][1] >= 1.f) ? 1.f : 0.f;
            if (FINAL) {
                hacc[c][0] = fmaf(WT[t], sp0, hacc[c][0]);
                hacc[c][1] = fmaf(WT[t], sp1, hacc[c][1]);
            } else {
                *(u64*)&hout[t][tid + 32 * c][0] = pack2(sp0, sp1);
            }
            v[c][0] *= (1.f - sp0);
            v[c][1] *= (1.f - sp1);
        }
    }
    __syncwarp();
}

__global__ __launch_bounds__(NTHREADS)
void snn_fused_kernel(
    const float* __restrict__ x,     // [B,S]
    const float* __restrict__ enc,   // [T,B,S]
    const float* __restrict__ W_in,  // [S,H]
    const float* __restrict__ b_in,  // [H]
    const float* __restrict__ W_r1, const float* __restrict__ b_r1,
    const float* __restrict__ g_r1, const float* __restrict__ be_r1,
    const float* __restrict__ W_r2, const float* __restrict__ b_r2,
    const float* __restrict__ g_r2, const float* __restrict__ be_r2,
    const float* __restrict__ W_out, const float* __restrict__ b_out,
    float* __restrict__ out)         // [B,A]
{
    __shared__ __align__(16) float spk[NT][NS][NR];   // 16 KB encoder spikes
    __shared__ __align__(16) float hb1[NT][NH][NR];   // 8 KB spikes after LIF1
    __shared__ __align__(16) float hb2[NT][NH][NR];   // 8 KB spikes after block1
    __shared__ float xs[NR][NS];        // 2 KB staged x rows
    __shared__ float ha[NR][NH];        // weighted spike accumulator

    const int tid = threadIdx.x;
    const int b0 = blockIdx.x * NR;

    // ---- Stage x rows ----
    #pragma unroll
    for (int r = 0; r < NR; r++)
        #pragma unroll
        for (int s = tid; s < NS; s += NTHREADS)
            xs[r][s] = x[(b0 + r) * NS + s];
    __syncwarp();

    // ---- Poisson encoder: spike = (enc_rand <= x) ----
    #pragma unroll
    for (int t = 0; t < NT; t++)
        #pragma unroll
        for (int r = 0; r < NR; r++)
            #pragma unroll
            for (int s = tid; s < NS; s += NTHREADS) {
                float e = enc[(t * NBATCH + (b0 + r)) * NS + s];
                spk[t][s][r] = (e <= xs[r][s]) ? 1.f : 0.f;
            }
    __syncwarp();

    // ---- Layer 1 GEMM: u2[t][c] = b_in + sum_s spk * W_in ----
    u64 u2[NT][NC];
    {
        float bin[NC];
        #pragma unroll
        for (int c = 0; c < NC; c++) bin[c] = b_in[tid + 32 * c];
        #pragma unroll
        for (int t = 0; t < NT; t++)
            #pragma unroll
            for (int c = 0; c < NC; c++)
                u2[t][c] = pack2(bin[c], bin[c]);

        #pragma unroll 2
        for (int s = 0; s < NS; s += 2) {
            u64 wA[NC], wB[NC];
            #pragma unroll
            for (int c = 0; c < NC; c++) {
                float a = W_in[s * NH + tid + 32 * c];
                float b = W_in[(s + 1) * NH + tid + 32 * c];
                wA[c] = pack2(a, a);
                wB[c] = pack2(b, b);
            }
            #pragma unroll
            for (int t = 0; t < NT; t++) {
                ulonglong2 p = *(const ulonglong2*)&spk[t][s][0];
                #pragma unroll
                for (int c = 0; c < NC; c++) {
                    fma2(u2[t][c], p.x, wA[c]);
                    fma2(u2[t][c], p.y, wB[c]);
                }
            }
        }
    }

    // ---- LIF1 ----
    {
        float v[NC][NR];
        #pragma unroll
        for (int c = 0; c < NC; c++) { v[c][0] = 0.f; v[c][1] = 0.f; }
        #pragma unroll
        for (int t = 0; t < NT; t++) {
            #pragma unroll
            for (int c = 0; c < NC; c++) {
                float ut0, ut1;
                unpack2(u2[t][c], ut0, ut1);
                v[c][0] += (ut0 - v[c][0]) * 0.5f;
                v[c][1] += (ut1 - v[c][1]) * 0.5f;
                float sp0 = (v[c][0] >= 1.f) ? 1.f : 0.f;
                float sp1 = (v[c][1] >= 1.f) ? 1.f : 0.f;
                *(u64*)&hb1[t][tid + 32 * c][0] = pack2(sp0, sp1);
                v[c][0] *= (1.f - sp0);
                v[c][1] *= (1.f - sp1);
            }
        }
    }
    __syncwarp();

    float hacc[NC][NR];
    #pragma unroll
    for (int c = 0; c < NC; c++) { hacc[c][0] = 0.f; hacc[c][1] = 0.f; }

    // ---- ResBlock 1: hb1 -> hb2 ----
    {
        float bb[NC], gg[NC], bt[NC];
        #pragma unroll
        for (int c = 0; c < NC; c++) {
            bb[c] = b_r1[tid + 32 * c];
            gg[c] = g_r1[tid + 32 * c];
            bt[c] = be_r1[tid + 32 * c];
        }
        res_block<false>(W_r1, bb, gg, bt, hb1, hb2, tid, hacc);
    }

    // ---- ResBlock 2 (final): hb2 -> weighted accumulator ----
    {
        float bb[NC], gg[NC], bt[NC];
        #pragma unroll
        for (int c = 0; c < NC; c++) {
            bb[c] = b_r2[tid + 32 * c];
            gg[c] = g_r2[tid + 32 * c];
            bt[c] = be_r2[tid + 32 * c];
        }
        res_block<true>(W_r2, bb, gg, bt, hb2, hb1, tid, hacc);
    }

    // ---- Output head: q[r][a] = sum_h hacc * W_out[h][a] + b_out[a]*SW ----
    #pragma unroll
    for (int c = 0; c < NC; c++) {
        ha[0][tid + 32 * c] = hacc[c][0];
        ha[1][tid + 32 * c] = hacc[c][1];
    }
    __syncwarp();

    #pragma unroll
    for (int idx = tid; idx < NR * NA; idx += NTHREADS) {
        int r = idx / NA, a = idx % NA;
        float sum = b_out[a] * SW_TOTAL;
        #pragma unroll
        for (int j = 0; j < NH; j++)
            sum = fmaf(ha[r][j], W_out[j * NA + a], sum);
        out[(b0 + r) * NA + a] = sum;
    }
}

extern "C" void kernel_launch(void* const* d_in, const int* in_sizes, int n_in,
                              void* d_out, int out_size)
{
    const float* x      = (const float*)d_in[0];
    const float* enc    = (const float*)d_in[1];
    const float* W_in   = (const float*)d_in[2];
    const float* b_in   = (const float*)d_in[3];
    const float* W_r1   = (const float*)d_in[4];
    const float* b_r1   = (const float*)d_in[5];
    const float* g_r1   = (const float*)d_in[6];
    const float* be_r1  = (const float*)d_in[7];
    const float* W_r2   = (const float*)d_in[8];
    const float* b_r2   = (const float*)d_in[9];
    const float* g_r2   = (const float*)d_in[10];
    const float* be_r2  = (const float*)d_in[11];
    const float* W_out  = (const float*)d_in[12];
    const float* b_out  = (const float*)d_in[13];
    float* out = (float*)d_out;

    dim3 grid(NBATCH / NR);
    dim3 block(NTHREADS);
    snn_fused_kernel<<<grid, block>>>(
        x, enc, W_in, b_in, W_r1, b_r1, g_r1, be_r1,
        W_r2, b_r2, g_r2, be_r2, W_out, b_out, out);
}

// round 15
// speedup vs baseline: 1.5112x; 1.4255x over previous
#include <cuda_runtime.h>

// Problem constants (fixed by the dataset)
#define NBATCH 16384
#define NS 256
#define NH 128
#define NA 18
#define NT 8
#define NR 2         // batch rows per block
#define NTHREADS 64  // 2 warps; warp w owns columns h = lane+64w, lane+64w+32
#define SCHUNK 128   // layer-1 spike staging chunk (2 passes over S=256)

// Folded non-spiking-LIF + mean-over-T weights: w_t = (1 - 2^{-(T-t)})/T
#define SW_TOTAL 0.87548828125f

typedef unsigned long long u64;

// ---- packed fp32x2 helpers (sm_103a) ----
__device__ __forceinline__ u64 pack2(float a, float b) {
    u64 r;
    asm("mov.b64 %0, {%1, %2};" : "=l"(r) : "f"(a), "f"(b));
    return r;
}
__device__ __forceinline__ void unpack2(u64 v, float& a, float& b) {
    asm("mov.b64 {%0, %1}, %2;" : "=f"(a), "=f"(b) : "l"(v));
}
__device__ __forceinline__ void fma2(u64& acc, u64 ab, u64 cd) {
    asm("fma.rn.f32x2 %0, %1, %2, %3;" : "=l"(acc) : "l"(ab), "l"(cd), "l"(acc));
}

// LN stats over NH=128 with 2 warps (each thread pre-sums its 2 columns).
// One __syncthreads per call; red is double-buffered by t parity.
__device__ __forceinline__ void ln_stats_2w(
    float s0, float q0, float s1, float q1,
    float (&red)[2][8], int t, int lane, int w,
    float& mu0, float& rs0, float& mu1, float& rs1)
{
    #pragma unroll
    for (int o = 16; o > 0; o >>= 1) {
        s0 += __shfl_xor_sync(0xffffffffu, s0, o);
        q0 += __shfl_xor_sync(0xffffffffu, q0, o);
        s1 += __shfl_xor_sync(0xffffffffu, s1, o);
        q1 += __shfl_xor_sync(0xffffffffu, q1, o);
    }
    float* rb = red[t & 1];
    if (lane == 0) {
        rb[w * 4 + 0] = s0; rb[w * 4 + 1] = q0;
        rb[w * 4 + 2] = s1; rb[w * 4 + 3] = q1;
    }
    __syncthreads();
    float S0 = rb[0] + rb[4], Q0 = rb[1] + rb[5];
    float S1 = rb[2] + rb[6], Q1 = rb[3] + rb[7];
    mu0 = S0 * (1.f / NH);
    mu1 = S1 * (1.f / NH);
    rs0 = rsqrtf(Q0 * (1.f / NH) - mu0 * mu0 + 1e-5f);
    rs1 = rsqrtf(Q1 * (1.f / NH) - mu1 * mu1 + 1e-5f);
}

// One MS_ResBlock for NR=2 rows, all NT timesteps, 2 columns per thread.
template <bool FINAL>
__device__ __forceinline__ void res_block(
    const float* __restrict__ W,
    const float (&bb)[2], const float (&gg)[2], const float (&bt)[2],
    const float (&hin)[NT][NH][NR], float (&hout)[NT][NH][NR],
    float (&red)[2][8], int h0, int h1, int lane, int w,
    float (&hacc)[2][2])
{
    constexpr float WT[NT] = {
        0.12451171875f, 0.1240234375f, 0.123046875f, 0.12109375f,
        0.1171875f, 0.109375f, 0.09375f, 0.0625f
    };

    // GEMM: u2[t][c] = bias + sum_j hin[t][j][:] * W[j][h_c]
    u64 u2[NT][2];
    #pragma unroll
    for (int t = 0; t < NT; t++) {
        u2[t][0] = pack2(bb[0], bb[0]);
        u2[t][1] = pack2(bb[1], bb[1]);
    }

    #pragma unroll 4
    for (int j = 0; j < NH; j += 2) {
        float a0 = W[j * NH + h0];
        float a1 = W[j * NH + h1];
        float c0 = W[(j + 1) * NH + h0];
        float c1 = W[(j + 1) * NH + h1];
        u64 wa0 = pack2(a0, a0), wa1 = pack2(a1, a1);
        u64 wc0 = pack2(c0, c0), wc1 = pack2(c1, c1);
        #pragma unroll
        for (int t = 0; t < NT; t++) {
            ulonglong2 p = *(const ulonglong2*)&hin[t][j][0];
            fma2(u2[t][0], p.x, wa0);
            fma2(u2[t][1], p.x, wa1);
            fma2(u2[t][0], p.y, wc0);
            fma2(u2[t][1], p.y, wc1);
        }
    }

    // LN + residual + LIF (sequential over t)
    float v[2][2] = {{0.f, 0.f}, {0.f, 0.f}};
    #pragma unroll
    for (int t = 0; t < NT; t++) {
        float u[2][2];   // u[c][r]
        unpack2(u2[t][0], u[0][0], u[0][1]);
        unpack2(u2[t][1], u[1][0], u[1][1]);
        float mu0, rs0, mu1, rs1;
        ln_stats_2w(u[0][0] + u[1][0], u[0][0] * u[0][0] + u[1][0] * u[1][0],
                    u[0][1] + u[1][1], u[0][1] * u[0][1] + u[1][1] * u[1][1],
                    red, t, lane, w, mu0, rs0, mu1, rs1);

        float r00, r01, r10, r11;
        unpack2(*(const u64*)&hin[t][h0][0], r00, r01);
        unpack2(*(const u64*)&hin[t][h1][0], r10, r11);

        float li00 = (u[0][0] - mu0) * rs0 * gg[0] + bt[0] + r00;
        float li01 = (u[0][1] - mu1) * rs1 * gg[0] + bt[0] + r01;
        float li10 = (u[1][0] - mu0) * rs0 * gg[1] + bt[1] + r10;
        float li11 = (u[1][1] - mu1) * rs1 * gg[1] + bt[1] + r11;

        v[0][0] += (li00 - v[0][0]) * 0.5f;
        v[0][1] += (li01 - v[0][1]) * 0.5f;
        v[1][0] += (li10 - v[1][0]) * 0.5f;
        v[1][1] += (li11 - v[1][1]) * 0.5f;

        float sp00 = (v[0][0] >= 1.f) ? 1.f : 0.f;
        float sp01 = (v[0][1] >= 1.f) ? 1.f : 0.f;
        float sp10 = (v[1][0] >= 1.f) ? 1.f : 0.f;
        float sp11 = (v[1][1] >= 1.f) ? 1.f : 0.f;

        if (FINAL) {
            hacc[0][0] = fmaf(WT[t], sp00, hacc[0][0]);
            hacc[0][1] = fmaf(WT[t], sp01, hacc[0][1]);
            hacc[1][0] = fmaf(WT[t], sp10, hacc[1][0]);
            hacc[1][1] = fmaf(WT[t], sp11, hacc[1][1]);
        } else {
            *(u64*)&hout[t][h0][0] = pack2(sp00, sp01);
            *(u64*)&hout[t][h1][0] = pack2(sp10, sp11);
        }
        v[0][0] *= (1.f - sp00);
        v[0][1] *= (1.f - sp01);
        v[1][0] *= (1.f - sp10);
        v[1][1] *= (1.f - sp11);
    }
    __syncthreads();
}

__global__ __launch_bounds__(NTHREADS, 9)
void snn_fused_kernel(
    const float* __restrict__ x,     // [B,S]
    const float* __restrict__ enc,   // [T,B,S]
    const float* __restrict__ W_in,  // [S,H]
    const float* __restrict__ b_in,  // [H]
    const float* __restrict__ W_r1, const float* __restrict__ b_r1,
    const float* __restrict__ g_r1, const float* __restrict__ be_r1,
    const float* __restrict__ W_r2, const float* __restrict__ b_r2,
    const float* __restrict__ g_r2, const float* __restrict__ be_r2,
    const float* __restrict__ W_out, const float* __restrict__ b_out,
    float* __restrict__ out)         // [B,A]
{
    __shared__ __align__(16) float spk[NT][SCHUNK][NR];  // 8 KB staged chunk
    __shared__ __align__(16) float hb1[NT][NH][NR];      // 8 KB spikes after LIF1
    __shared__ __align__(16) float hb2[NT][NH][NR];      // 8 KB spikes after block1
    __shared__ float red[2][8];       // LN cross-warp scratch (double-buffered)
    __shared__ float ha[NR][NH];      // 1 KB weighted spike accumulator

    const int tid = threadIdx.x;
    const int lane = tid & 31, w = tid >> 5;
    const int h0 = lane + 64 * w, h1 = h0 + 32;
    const int b0 = blockIdx.x * NR;

    // ---- Layer 1 GEMM with chunked encoder staging ----
    u64 u2[NT][2];
    {
        const float bin0 = b_in[h0], bin1 = b_in[h1];
        #pragma unroll
        for (int t = 0; t < NT; t++) {
            u2[t][0] = pack2(bin0, bin0);
            u2[t][1] = pack2(bin1, bin1);
        }
    }

    #pragma unroll
    for (int chunk = 0; chunk < NS / SCHUNK; chunk++) {
        // Fill spike chunk: spike = (enc_rand <= x), fresh noise per t
        #pragma unroll
        for (int r = 0; r < NR; r++)
            #pragma unroll
            for (int si = tid; si < SCHUNK; si += NTHREADS) {
                float xv = x[(b0 + r) * NS + chunk * SCHUNK + si];
                #pragma unroll
                for (int t = 0; t < NT; t++) {
                    float e = enc[(t * NBATCH + (b0 + r)) * NS + chunk * SCHUNK + si];
                    spk[t][si][r] = (e <= xv) ? 1.f : 0.f;
                }
            }
        __syncthreads();

        // Accumulate this chunk
        #pragma unroll 4
        for (int j = 0; j < SCHUNK; j += 2) {
            int gj = chunk * SCHUNK + j;
            float a0 = W_in[gj * NH + h0];
            float a1 = W_in[gj * NH + h1];
            float c0 = W_in[(gj + 1) * NH + h0];
            float c1 = W_in[(gj + 1) * NH + h1];
            u64 wa0 = pack2(a0, a0), wa1 = pack2(a1, a1);
            u64 wc0 = pack2(c0, c0), wc1 = pack2(c1, c1);
            #pragma unroll
            for (int t = 0; t < NT; t++) {
                ulonglong2 p = *(const ulonglong2*)&spk[t][j][0];
                fma2(u2[t][0], p.x, wa0);
                fma2(u2[t][1], p.x, wa1);
                fma2(u2[t][0], p.y, wc0);
                fma2(u2[t][1], p.y, wc1);
            }
        }
        __syncthreads();
    }

    // ---- LIF1: v += (u - v)/2; spike = (v >= 1); hard reset -> hb1 ----
    {
        float v[2][2] = {{0.f, 0.f}, {0.f, 0.f}};
        #pragma unroll
        for (int t = 0; t < NT; t++) {
            float u00, u01, u10, u11;
            unpack2(u2[t][0], u00, u01);
            unpack2(u2[t][1], u10, u11);
            v[0][0] += (u00 - v[0][0]) * 0.5f;
            v[0][1] += (u01 - v[0][1]) * 0.5f;
            v[1][0] += (u10 - v[1][0]) * 0.5f;
            v[1][1] += (u11 - v[1][1]) * 0.5f;
            float sp00 = (v[0][0] >= 1.f) ? 1.f : 0.f;
            float sp01 = (v[0][1] >= 1.f) ? 1.f : 0.f;
            float sp10 = (v[1][0] >= 1.f) ? 1.f : 0.f;
            float sp11 = (v[1][1] >= 1.f) ? 1.f : 0.f;
            *(u64*)&hb1[t][h0][0] = pack2(sp00, sp01);
            *(u64*)&hb1[t][h1][0] = pack2(sp10, sp11);
            v[0][0] *= (1.f - sp00);
            v[0][1] *= (1.f - sp01);
            v[1][0] *= (1.f - sp10);
            v[1][1] *= (1.f - sp11);
        }
    }
    __syncthreads();

    float hacc[2][2] = {{0.f, 0.f}, {0.f, 0.f}};

    // ---- ResBlock 1: hb1 -> hb2 ----
    {
        const float bb[2] = {b_r1[h0], b_r1[h1]};
        const float gg[2] = {g_r1[h0], g_r1[h1]};
        const float bt[2] = {be_r1[h0], be_r1[h1]};
        res_block<false>(W_r1, bb, gg, bt, hb1, hb2, red, h0, h1, lane, w, hacc);
    }

    // ---- ResBlock 2 (final): hb2 -> weighted accumulator ----
    {
        const float bb[2] = {b_r2[h0], b_r2[h1]};
        const float gg[2] = {g_r2[h0], g_r2[h1]};
        const float bt[2] = {be_r2[h0], be_r2[h1]};
        res_block<true>(W_r2, bb, gg, bt, hb2, hb1, red, h0, h1, lane, w, hacc);
    }

    // ---- Output head: q[r][a] = sum_h hacc * W_out[h][a] + b_out[a]*SW ----
    ha[0][h0] = hacc[0][0];
    ha[1][h0] = hacc[0][1];
    ha[0][h1] = hacc[1][0];
    ha[1][h1] = hacc[1][1];
    __syncthreads();

    if (tid < NR * NA) {
        int r = tid / NA, a = tid % NA;
        float sum = b_out[a] * SW_TOTAL;
        #pragma unroll
        for (int j = 0; j < NH; j++)
            sum = fmaf(ha[r][j], W_out[j * NA + a], sum);
        out[(b0 + r) * NA + a] = sum;
    }
}

extern "C" void kernel_launch(void* const* d_in, const int* in_sizes, int n_in,
                              void* d_out, int out_size)
{
    const float* x      = (const float*)d_in[0];
    const float* enc    = (const float*)d_in[1];
    const float* W_in   = (const float*)d_in[2];
    const float* b_in   = (const float*)d_in[3];
    const float* W_r1   = (const float*)d_in[4];
    const float* b_r1   = (const float*)d_in[5];
    const float* g_r1   = (const float*)d_in[6];
    const float* be_r1  = (const float*)d_in[7];
    const float* W_r2   = (const float*)d_in[8];
    const float* b_r2   = (const float*)d_in[9];
    const float* g_r2   = (const float*)d_in[10];
    const float* be_r2  = (const float*)d_in[11];
    const float* W_out  = (const float*)d_in[12];
    const float* b_out  = (const float*)d_in[13];
    float* out = (float*)d_out;

    dim3 grid(NBATCH / NR);
    dim3 block(NTHREADS);
    snn_fused_kernel<<<grid, block>>>(
        x, enc, W_in, b_in, W_r1, b_r1, g_r1, be_r1,
        W_r2, b_r2, g_r2, be_r2, W_out, b_out, out);
}